// round 4
// baseline (speedup 1.0000x reference)
#include <cuda_runtime.h>
#include <cuda_bf16.h>
#include <math.h>

#define NN 50000
#define EE 1600000
#define DIM 128
#define HEADS 4
#define ODIM 32
#define ALPHA 0.2f
#define WPB 8   // warps per block in agg

// ---------------- device scratch ----------------
__device__ __align__(16) float g_H[NN * DIM];     // projected features (25.6 MB)
__device__ __align__(16) float g_Hs[NN * HEADS];  // per-node src scores
__device__ __align__(16) float g_Ht[NN * HEADS];  // per-node tgt scores
__device__ int g_cnt[NN];        // out-degree histogram
__device__ int g_off[NN + 1];    // CSR offsets
__device__ int g_cur[NN];        // scatter cursors
__device__ int g_csr[EE];        // tgt indices grouped by src
__device__ unsigned g_maxenc;    // order-preserving global max

__device__ __forceinline__ unsigned enc_f(float f) {
    unsigned u = __float_as_uint(f);
    return (u & 0x80000000u) ? ~u : (u | 0x80000000u);
}
__device__ __forceinline__ float dec_f(unsigned u) {
    return (u & 0x80000000u) ? __uint_as_float(u ^ 0x80000000u)
                             : __uint_as_float(~u);
}
__device__ __forceinline__ float lrelu(float x) { return x > 0.f ? x : ALPHA * x; }

// ---------------- K0: init (counters only) ----------------
__global__ void init_kernel() {
    int i = blockIdx.x * blockDim.x + threadIdx.x;
    if (i == 0) g_maxenc = 0u;
    if (i < NN) g_cnt[i] = 0;
}

// ---------------- K1: GEMM  H = X @ W ----------------
__global__ __launch_bounds__(256) void gemm_kernel(const float* __restrict__ X,
                                                   const float* __restrict__ W) {
    __shared__ __align__(16) float Xs[16][132];
    __shared__ __align__(16) float Ws[16][128];
    const int m0 = blockIdx.x * 128;
    const int tid = threadIdx.x;
    const int tx = tid & 15;
    const int ty = tid >> 4;
    float acc[8][8];
#pragma unroll
    for (int i = 0; i < 8; i++)
#pragma unroll
        for (int j = 0; j < 8; j++) acc[i][j] = 0.0f;

    for (int k0 = 0; k0 < DIM; k0 += 16) {
#pragma unroll
        for (int j = 0; j < 2; j++) {
            int s = tid * 2 + j;
            int m = s >> 2;
            int kk4 = (s & 3) * 4;
            float4 v = make_float4(0.f, 0.f, 0.f, 0.f);
            int gm = m0 + m;
            if (gm < NN) v = *(const float4*)(X + (size_t)gm * DIM + k0 + kk4);
            Xs[kk4 + 0][m] = v.x;
            Xs[kk4 + 1][m] = v.y;
            Xs[kk4 + 2][m] = v.z;
            Xs[kk4 + 3][m] = v.w;
            int wk = s >> 5;
            int wc = (s & 31) * 4;
            *(float4*)&Ws[wk][wc] = *(const float4*)(W + (size_t)(k0 + wk) * DIM + wc);
        }
        __syncthreads();
#pragma unroll
        for (int kk = 0; kk < 16; kk++) {
            float a[8], b[8];
            *(float4*)(a)     = *(float4*)&Xs[kk][ty * 8];
            *(float4*)(a + 4) = *(float4*)&Xs[kk][ty * 8 + 4];
            *(float4*)(b)     = *(float4*)&Ws[kk][tx * 8];
            *(float4*)(b + 4) = *(float4*)&Ws[kk][tx * 8 + 4];
#pragma unroll
            for (int i = 0; i < 8; i++)
#pragma unroll
                for (int j = 0; j < 8; j++) acc[i][j] = fmaf(a[i], b[j], acc[i][j]);
        }
        __syncthreads();
    }
#pragma unroll
    for (int i = 0; i < 8; i++) {
        int gm = m0 + ty * 8 + i;
        if (gm < NN) {
            float4 v0 = make_float4(acc[i][0], acc[i][1], acc[i][2], acc[i][3]);
            float4 v1 = make_float4(acc[i][4], acc[i][5], acc[i][6], acc[i][7]);
            *(float4*)(g_H + (size_t)gm * DIM + tx * 8)     = v0;
            *(float4*)(g_H + (size_t)gm * DIM + tx * 8 + 4) = v1;
        }
    }
}

// ---------------- K2: per-node attention scores ----------------
__global__ void score_kernel(const float* __restrict__ Al, const float* __restrict__ Ar) {
    int idx = blockIdx.x * blockDim.x + threadIdx.x;
    if (idx >= NN * HEADS) return;
    int n = idx >> 2;
    int h = idx & 3;
    const float4* Hp = (const float4*)(g_H + (size_t)n * DIM + h * ODIM);
    const float4* Ap = (const float4*)(Al + h * ODIM);
    const float4* Bp = (const float4*)(Ar + h * ODIM);
    float s = 0.f, t = 0.f;
#pragma unroll
    for (int i = 0; i < 8; i++) {
        float4 v = Hp[i];
        float4 a = Ap[i];
        float4 b = Bp[i];
        s += v.x * a.x + v.y * a.y + v.z * a.z + v.w * a.w;
        t += v.x * b.x + v.y * b.y + v.z * b.z + v.w * b.w;
    }
    g_Hs[idx] = s;
    g_Ht[idx] = t;
}

// ---------------- K3: histogram of src counts ----------------
__global__ void hist_kernel(const int* __restrict__ ei) {
    int e = blockIdx.x * blockDim.x + threadIdx.x;
    if (e < EE) atomicAdd(&g_cnt[ei[e]], 1);
}

// ---------------- K4: exclusive scan (single block) ----------------
__global__ __launch_bounds__(1024) void scan_kernel() {
    __shared__ int s[1024];
    int t = threadIdx.x;
    int beg = t * 49;
    int end2 = min(beg + 49, NN);
    int sum = 0;
    for (int i = beg; i < end2; i++) sum += g_cnt[i];
    s[t] = sum;
    __syncthreads();
    for (int off = 1; off < 1024; off <<= 1) {
        int v = 0;
        if (t >= off) v = s[t - off];
        __syncthreads();
        s[t] += v;
        __syncthreads();
    }
    int prefix = (t == 0) ? 0 : s[t - 1];
    for (int i = beg; i < end2; i++) {
        int c = g_cnt[i];
        g_off[i] = prefix;
        g_cur[i] = prefix;
        prefix += c;
    }
    if (t == 1023) g_off[NN] = EE;
}

// ---------------- K5: scatter edges into CSR + global max ----------------
__global__ void scatter_kernel(const int* __restrict__ ei) {
    int e = blockIdx.x * blockDim.x + threadIdx.x;
    float m = -1e30f;
    if (e < EE) {
        int src = ei[e];
        int tgt = ei[EE + e];
        int p = atomicAdd(&g_cur[src], 1);
        g_csr[p] = tgt;
        float4 hs = *(const float4*)(g_Hs + (size_t)src * 4);
        float4 ht = *(const float4*)(g_Ht + (size_t)tgt * 4);
        m = fmaxf(m, lrelu(hs.x + ht.x));
        m = fmaxf(m, lrelu(hs.y + ht.y));
        m = fmaxf(m, lrelu(hs.z + ht.z));
        m = fmaxf(m, lrelu(hs.w + ht.w));
    }
#pragma unroll
    for (int o = 16; o > 0; o >>= 1)
        m = fmaxf(m, __shfl_xor_sync(0xffffffffu, m, o));
    __shared__ float sm[8];
    int lane = threadIdx.x & 31, wid = threadIdx.x >> 5;
    if (lane == 0) sm[wid] = m;
    __syncthreads();
    if (wid == 0) {
        m = (lane < (blockDim.x >> 5)) ? sm[lane] : -1e30f;
#pragma unroll
        for (int o = 4; o > 0; o >>= 1)
            m = fmaxf(m, __shfl_xor_sync(0xffffffffu, m, o));
        if (lane == 0) atomicMax(&g_maxenc, enc_f(m));
    }
}

// ---------------- K6: fused denom + aggregation + ELU (warp per node) ----------------
__global__ __launch_bounds__(WPB * 32) void agg_kernel(float* __restrict__ out) {
    __shared__ int   s_tgt[WPB][32];
    __shared__ float s_e[WPB][32][4];
    int wid  = threadIdx.x >> 5;
    int lane = threadIdx.x & 31;
    int node = blockIdx.x * WPB + wid;
    if (node >= NN) return;
    int h = lane >> 3;               // head owned by this lane's output cols
    int start = g_off[node];
    int end   = g_off[node + 1];
    float gmax = dec_f(g_maxenc);
    float4 hs = *(const float4*)(g_Hs + (size_t)node * 4);

    float4 acc = make_float4(0.f, 0.f, 0.f, 0.f);
    float4 dsum = make_float4(0.f, 0.f, 0.f, 0.f);

    for (int base = start; base < end; base += 32) {
        int cnt = min(32, end - base);
        int tgt = 0;
        float4 e4 = make_float4(0.f, 0.f, 0.f, 0.f);
        if (lane < cnt) {
            tgt = g_csr[base + lane];
            float4 ht = *(const float4*)(g_Ht + (size_t)tgt * 4);
            e4.x = __expf(lrelu(hs.x + ht.x) - gmax);
            e4.y = __expf(lrelu(hs.y + ht.y) - gmax);
            e4.z = __expf(lrelu(hs.z + ht.z) - gmax);
            e4.w = __expf(lrelu(hs.w + ht.w) - gmax);
            dsum.x += e4.x; dsum.y += e4.y; dsum.z += e4.z; dsum.w += e4.w;
        }
        s_tgt[wid][lane] = tgt;
        s_e[wid][lane][0] = e4.x;
        s_e[wid][lane][1] = e4.y;
        s_e[wid][lane][2] = e4.z;
        s_e[wid][lane][3] = e4.w;
        __syncwarp();
#pragma unroll 4
        for (int j = 0; j < cnt; j++) {
            int t = s_tgt[wid][j];
            float ej = s_e[wid][j][h];
            float4 v = *(const float4*)(g_H + (size_t)t * DIM + lane * 4);
            acc.x = fmaf(ej, v.x, acc.x);
            acc.y = fmaf(ej, v.y, acc.y);
            acc.z = fmaf(ej, v.z, acc.z);
            acc.w = fmaf(ej, v.w, acc.w);
        }
        __syncwarp();
    }

    // warp-reduce dsum (all lanes end with full sums)
#pragma unroll
    for (int o = 16; o > 0; o >>= 1) {
        dsum.x += __shfl_xor_sync(0xffffffffu, dsum.x, o);
        dsum.y += __shfl_xor_sync(0xffffffffu, dsum.y, o);
        dsum.z += __shfl_xor_sync(0xffffffffu, dsum.z, o);
        dsum.w += __shfl_xor_sync(0xffffffffu, dsum.w, o);
    }
    float dh = (h == 0) ? dsum.x : (h == 1) ? dsum.y : (h == 2) ? dsum.z : dsum.w;
    float sc = 1.0f / (dh + 1e-8f);
    acc.x *= sc; acc.y *= sc; acc.z *= sc; acc.w *= sc;
    acc.x = acc.x > 0.f ? acc.x : expm1f(acc.x);
    acc.y = acc.y > 0.f ? acc.y : expm1f(acc.y);
    acc.z = acc.z > 0.f ? acc.z : expm1f(acc.z);
    acc.w = acc.w > 0.f ? acc.w : expm1f(acc.w);
    *(float4*)(out + (size_t)node * DIM + lane * 4) = acc;
}

extern "C" void kernel_launch(void* const* d_in, const int* in_sizes, int n_in,
                              void* d_out, int out_size) {
    const float* X  = (const float*)d_in[0];
    const int* EI   = (const int*)d_in[1];
    const float* W  = (const float*)d_in[2];
    const float* Al = (const float*)d_in[3];
    const float* Ar = (const float*)d_in[4];
    float* out = (float*)d_out;

    init_kernel<<<(NN + 255) / 256, 256>>>();
    gemm_kernel<<<(NN + 127) / 128, 256>>>(X, W);
    score_kernel<<<(NN * HEADS + 255) / 256, 256>>>(Al, Ar);
    hist_kernel<<<(EE + 255) / 256, 256>>>(EI);
    scan_kernel<<<1, 1024>>>();
    scatter_kernel<<<(EE + 255) / 256, 256>>>(EI);
    agg_kernel<<<(NN + WPB - 1) / WPB, WPB * 32>>>(out);
}

// round 5
// speedup vs baseline: 1.0815x; 1.0815x over previous
#include <cuda_runtime.h>
#include <cuda_fp16.h>
#include <math.h>

#define NN 50000
#define EE 1600000
#define DIM 128
#define HEADS 4
#define ODIM 32
#define ALPHA 0.2f
#define WPB 8   // warps per block in agg

// ---------------- device scratch ----------------
__device__ __align__(16) float  g_H[NN * DIM];     // fp32 features (25.6 MB) for scores
__device__ __align__(16) __half g_Hh[NN * DIM];    // fp16 features (12.8 MB) for gathers
__device__ __align__(16) float  g_Hs[NN * HEADS];
__device__ __align__(16) float  g_Ht[NN * HEADS];
__device__ int g_cnt[NN];
__device__ int g_off[NN + 1];
__device__ int g_cur[NN];
__device__ int g_csr[EE];
__device__ unsigned g_maxenc;

__device__ __forceinline__ unsigned enc_f(float f) {
    unsigned u = __float_as_uint(f);
    return (u & 0x80000000u) ? ~u : (u | 0x80000000u);
}
__device__ __forceinline__ float dec_f(unsigned u) {
    return (u & 0x80000000u) ? __uint_as_float(u ^ 0x80000000u)
                             : __uint_as_float(~u);
}
__device__ __forceinline__ float lrelu(float x) { return x > 0.f ? x : ALPHA * x; }

// ---------------- K0: init ----------------
__global__ void init_kernel() {
    int i = blockIdx.x * blockDim.x + threadIdx.x;
    if (i == 0) g_maxenc = 0u;
    if (i < NN) g_cnt[i] = 0;
}

// ---------------- K1: GEMM  H = X @ W  (+ fp16 copy) ----------------
__global__ __launch_bounds__(256) void gemm_kernel(const float* __restrict__ X,
                                                   const float* __restrict__ W) {
    __shared__ __align__(16) float Xs[16][132];
    __shared__ __align__(16) float Ws[16][128];
    const int m0 = blockIdx.x * 128;
    const int tid = threadIdx.x;
    const int tx = tid & 15;
    const int ty = tid >> 4;
    float acc[8][8];
#pragma unroll
    for (int i = 0; i < 8; i++)
#pragma unroll
        for (int j = 0; j < 8; j++) acc[i][j] = 0.0f;

    for (int k0 = 0; k0 < DIM; k0 += 16) {
#pragma unroll
        for (int j = 0; j < 2; j++) {
            int s = tid * 2 + j;
            int m = s >> 2;
            int kk4 = (s & 3) * 4;
            float4 v = make_float4(0.f, 0.f, 0.f, 0.f);
            int gm = m0 + m;
            if (gm < NN) v = *(const float4*)(X + (size_t)gm * DIM + k0 + kk4);
            Xs[kk4 + 0][m] = v.x;
            Xs[kk4 + 1][m] = v.y;
            Xs[kk4 + 2][m] = v.z;
            Xs[kk4 + 3][m] = v.w;
            int wk = s >> 5;
            int wc = (s & 31) * 4;
            *(float4*)&Ws[wk][wc] = *(const float4*)(W + (size_t)(k0 + wk) * DIM + wc);
        }
        __syncthreads();
#pragma unroll
        for (int kk = 0; kk < 16; kk++) {
            float a[8], b[8];
            *(float4*)(a)     = *(float4*)&Xs[kk][ty * 8];
            *(float4*)(a + 4) = *(float4*)&Xs[kk][ty * 8 + 4];
            *(float4*)(b)     = *(float4*)&Ws[kk][tx * 8];
            *(float4*)(b + 4) = *(float4*)&Ws[kk][tx * 8 + 4];
#pragma unroll
            for (int i = 0; i < 8; i++)
#pragma unroll
                for (int j = 0; j < 8; j++) acc[i][j] = fmaf(a[i], b[j], acc[i][j]);
        }
        __syncthreads();
    }
#pragma unroll
    for (int i = 0; i < 8; i++) {
        int gm = m0 + ty * 8 + i;
        if (gm < NN) {
            float4 v0 = make_float4(acc[i][0], acc[i][1], acc[i][2], acc[i][3]);
            float4 v1 = make_float4(acc[i][4], acc[i][5], acc[i][6], acc[i][7]);
            *(float4*)(g_H + (size_t)gm * DIM + tx * 8)     = v0;
            *(float4*)(g_H + (size_t)gm * DIM + tx * 8 + 4) = v1;
            __half2 h0 = __float22half2_rn(make_float2(v0.x, v0.y));
            __half2 h1 = __float22half2_rn(make_float2(v0.z, v0.w));
            __half2 h2 = __float22half2_rn(make_float2(v1.x, v1.y));
            __half2 h3 = __float22half2_rn(make_float2(v1.z, v1.w));
            __half2* hp = (__half2*)(g_Hh + (size_t)gm * DIM + tx * 8);
            hp[0] = h0; hp[1] = h1; hp[2] = h2; hp[3] = h3;
        }
    }
}

// ---------------- K2: per-node attention scores ----------------
__global__ void score_kernel(const float* __restrict__ Al, const float* __restrict__ Ar) {
    int idx = blockIdx.x * blockDim.x + threadIdx.x;
    if (idx >= NN * HEADS) return;
    int n = idx >> 2;
    int h = idx & 3;
    const float4* Hp = (const float4*)(g_H + (size_t)n * DIM + h * ODIM);
    const float4* Ap = (const float4*)(Al + h * ODIM);
    const float4* Bp = (const float4*)(Ar + h * ODIM);
    float s = 0.f, t = 0.f;
#pragma unroll
    for (int i = 0; i < 8; i++) {
        float4 v = Hp[i];
        float4 a = Ap[i];
        float4 b = Bp[i];
        s += v.x * a.x + v.y * a.y + v.z * a.z + v.w * a.w;
        t += v.x * b.x + v.y * b.y + v.z * b.z + v.w * b.w;
    }
    g_Hs[idx] = s;
    g_Ht[idx] = t;
}

// ---------------- K3: histogram ----------------
__global__ void hist_kernel(const int* __restrict__ ei) {
    int e = blockIdx.x * blockDim.x + threadIdx.x;
    if (e < EE) atomicAdd(&g_cnt[ei[e]], 1);
}

// ---------------- K4: exclusive scan (single block) ----------------
__global__ __launch_bounds__(1024) void scan_kernel() {
    __shared__ int s[1024];
    int t = threadIdx.x;
    int beg = t * 49;
    int end2 = min(beg + 49, NN);
    int sum = 0;
    for (int i = beg; i < end2; i++) sum += g_cnt[i];
    s[t] = sum;
    __syncthreads();
    for (int off = 1; off < 1024; off <<= 1) {
        int v = 0;
        if (t >= off) v = s[t - off];
        __syncthreads();
        s[t] += v;
        __syncthreads();
    }
    int prefix = (t == 0) ? 0 : s[t - 1];
    for (int i = beg; i < end2; i++) {
        int c = g_cnt[i];
        g_off[i] = prefix;
        g_cur[i] = prefix;
        prefix += c;
    }
    if (t == 1023) g_off[NN] = EE;
}

// ---------------- K5: scatter edges into CSR + global max ----------------
__global__ void scatter_kernel(const int* __restrict__ ei) {
    int e = blockIdx.x * blockDim.x + threadIdx.x;
    float m = -1e30f;
    if (e < EE) {
        int src = ei[e];
        int tgt = ei[EE + e];
        int p = atomicAdd(&g_cur[src], 1);
        g_csr[p] = tgt;
        float4 hs = *(const float4*)(g_Hs + (size_t)src * 4);
        float4 ht = *(const float4*)(g_Ht + (size_t)tgt * 4);
        m = fmaxf(m, lrelu(hs.x + ht.x));
        m = fmaxf(m, lrelu(hs.y + ht.y));
        m = fmaxf(m, lrelu(hs.z + ht.z));
        m = fmaxf(m, lrelu(hs.w + ht.w));
    }
#pragma unroll
    for (int o = 16; o > 0; o >>= 1)
        m = fmaxf(m, __shfl_xor_sync(0xffffffffu, m, o));
    __shared__ float sm[8];
    int lane = threadIdx.x & 31, wid = threadIdx.x >> 5;
    if (lane == 0) sm[wid] = m;
    __syncthreads();
    if (wid == 0) {
        m = (lane < (blockDim.x >> 5)) ? sm[lane] : -1e30f;
#pragma unroll
        for (int o = 4; o > 0; o >>= 1)
            m = fmaxf(m, __shfl_xor_sync(0xffffffffu, m, o));
        if (lane == 0) atomicMax(&g_maxenc, enc_f(m));
    }
}

// ---------------- K6: fused denom + aggregation + ELU (warp per node) ----------------
__device__ __forceinline__ void agg_step(int wid, int j, int lane, int h,
                                         const int* s_tgt, const float* s_e,
                                         float4& acc) {
    int t = s_tgt[j];
    float ej = s_e[j * 4 + h];
    const __half2* hp = (const __half2*)(g_Hh + (size_t)t * DIM + lane * 4);
    __half2 a = hp[0], b = hp[1];
    float2 fa = __half22float2(a);
    float2 fb = __half22float2(b);
    acc.x = fmaf(ej, fa.x, acc.x);
    acc.y = fmaf(ej, fa.y, acc.y);
    acc.z = fmaf(ej, fb.x, acc.z);
    acc.w = fmaf(ej, fb.y, acc.w);
}

__global__ __launch_bounds__(WPB * 32) void agg_kernel(float* __restrict__ out) {
    __shared__ int   s_tgt[WPB][32];
    __shared__ float s_e[WPB][32 * 4];
    int wid  = threadIdx.x >> 5;
    int lane = threadIdx.x & 31;
    int node = blockIdx.x * WPB + wid;
    if (node >= NN) return;
    int h = lane >> 3;
    int start = g_off[node];
    int end   = g_off[node + 1];
    float gmax = dec_f(g_maxenc);
    float4 hs = *(const float4*)(g_Hs + (size_t)node * 4);

    float4 acc = make_float4(0.f, 0.f, 0.f, 0.f);
    float4 dsum = make_float4(0.f, 0.f, 0.f, 0.f);

    for (int base = start; base < end; base += 32) {
        int cnt = min(32, end - base);
        int tgt = 0;
        float4 e4 = make_float4(0.f, 0.f, 0.f, 0.f);
        if (lane < cnt) {
            tgt = g_csr[base + lane];
            float4 ht = *(const float4*)(g_Ht + (size_t)tgt * 4);
            e4.x = __expf(lrelu(hs.x + ht.x) - gmax);
            e4.y = __expf(lrelu(hs.y + ht.y) - gmax);
            e4.z = __expf(lrelu(hs.z + ht.z) - gmax);
            e4.w = __expf(lrelu(hs.w + ht.w) - gmax);
            dsum.x += e4.x; dsum.y += e4.y; dsum.z += e4.z; dsum.w += e4.w;
        }
        s_tgt[wid][lane] = tgt;
        *(float4*)&s_e[wid][lane * 4] = e4;
        __syncwarp();
        if (cnt == 32) {
#pragma unroll
            for (int j = 0; j < 32; j++)
                agg_step(wid, j, lane, h, s_tgt[wid], s_e[wid], acc);
        } else {
#pragma unroll 8
            for (int j = 0; j < cnt; j++)
                agg_step(wid, j, lane, h, s_tgt[wid], s_e[wid], acc);
        }
        __syncwarp();
    }

#pragma unroll
    for (int o = 16; o > 0; o >>= 1) {
        dsum.x += __shfl_xor_sync(0xffffffffu, dsum.x, o);
        dsum.y += __shfl_xor_sync(0xffffffffu, dsum.y, o);
        dsum.z += __shfl_xor_sync(0xffffffffu, dsum.z, o);
        dsum.w += __shfl_xor_sync(0xffffffffu, dsum.w, o);
    }
    float dh = (h == 0) ? dsum.x : (h == 1) ? dsum.y : (h == 2) ? dsum.z : dsum.w;
    float sc = 1.0f / (dh + 1e-8f);
    acc.x *= sc; acc.y *= sc; acc.z *= sc; acc.w *= sc;
    acc.x = acc.x > 0.f ? acc.x : expm1f(acc.x);
    acc.y = acc.y > 0.f ? acc.y : expm1f(acc.y);
    acc.z = acc.z > 0.f ? acc.z : expm1f(acc.z);
    acc.w = acc.w > 0.f ? acc.w : expm1f(acc.w);
    *(float4*)(out + (size_t)node * DIM + lane * 4) = acc;
}

extern "C" void kernel_launch(void* const* d_in, const int* in_sizes, int n_in,
                              void* d_out, int out_size) {
    const float* X  = (const float*)d_in[0];
    const int* EI   = (const int*)d_in[1];
    const float* W  = (const float*)d_in[2];
    const float* Al = (const float*)d_in[3];
    const float* Ar = (const float*)d_in[4];
    float* out = (float*)d_out;

    init_kernel<<<(NN + 255) / 256, 256>>>();
    gemm_kernel<<<(NN + 127) / 128, 256>>>(X, W);
    score_kernel<<<(NN * HEADS + 255) / 256, 256>>>(Al, Ar);
    hist_kernel<<<(EE + 255) / 256, 256>>>(EI);
    scan_kernel<<<1, 1024>>>();
    scatter_kernel<<<(EE + 255) / 256, 256>>>(EI);
    agg_kernel<<<(NN + WPB - 1) / WPB, WPB * 32>>>(out);
}